// round 1
// baseline (speedup 1.0000x reference)
#include <cuda_runtime.h>
#include <cstdint>

// QLinear: out[M,N] = x[M,K] @ W[N,K]^T + bias[N]
// M=8192, K=1024, N=4096 (all divisible by tile dims -> no bounds checks)
//
// Round 0 baseline: classic register-blocked fp32 SGEMM.
// 128x128 CTA tile, BK=16, 256 threads, 8x8 per-thread micro-tile.

#define BM 128
#define BN 128
#define BK 16
#define TM 8
#define TN 8

__global__ __launch_bounds__(256, 2)
void qlinear_sgemm_kernel(const float* __restrict__ A,     // [M,K] x
                          const float* __restrict__ B,     // [N,K] weight
                          const float* __restrict__ bias,  // [N]
                          float* __restrict__ C,           // [M,N]
                          int M, int N, int K)
{
    __shared__ float As[BK][BM];   // transposed A tile: As[k][m]
    __shared__ float Bs[BK][BN];   // transposed B tile: Bs[k][n]

    const int tid = threadIdx.x;
    const int tx  = tid & 15;          // 0..15 -> N direction
    const int ty  = tid >> 4;          // 0..15 -> M direction
    const int bm  = blockIdx.y * BM;
    const int bn  = blockIdx.x * BN;

    const float* Ab = A + (size_t)bm * K;
    const float* Bb = B + (size_t)bn * K;

    float acc[TM][TN];
    #pragma unroll
    for (int i = 0; i < TM; i++)
        #pragma unroll
        for (int j = 0; j < TN; j++)
            acc[i][j] = 0.0f;

    float a_frag[TM];
    float b_frag[TN];

    for (int kt = 0; kt < K; kt += BK) {
        // ---- load A tile: 128 rows x 16 k, via float4 (512 float4s / 256 thr = 2 each)
        #pragma unroll
        for (int i = 0; i < 2; i++) {
            int idx = tid + i * 256;
            int row = idx >> 2;              // 0..127
            int kc  = (idx & 3) << 2;        // 0,4,8,12
            float4 v = *reinterpret_cast<const float4*>(Ab + (size_t)row * K + kt + kc);
            As[kc + 0][row] = v.x;
            As[kc + 1][row] = v.y;
            As[kc + 2][row] = v.z;
            As[kc + 3][row] = v.w;
        }
        // ---- load B tile: 128 rows x 16 k
        #pragma unroll
        for (int i = 0; i < 2; i++) {
            int idx = tid + i * 256;
            int row = idx >> 2;
            int kc  = (idx & 3) << 2;
            float4 v = *reinterpret_cast<const float4*>(Bb + (size_t)row * K + kt + kc);
            Bs[kc + 0][row] = v.x;
            Bs[kc + 1][row] = v.y;
            Bs[kc + 2][row] = v.z;
            Bs[kc + 3][row] = v.w;
        }
        __syncthreads();

        // ---- compute: 16 k-steps, 8x8 FMAs each
        #pragma unroll
        for (int k = 0; k < BK; k++) {
            *reinterpret_cast<float4*>(&a_frag[0]) =
                *reinterpret_cast<const float4*>(&As[k][ty * TM]);
            *reinterpret_cast<float4*>(&a_frag[4]) =
                *reinterpret_cast<const float4*>(&As[k][ty * TM + 4]);
            *reinterpret_cast<float4*>(&b_frag[0]) =
                *reinterpret_cast<const float4*>(&Bs[k][tx * TN]);
            *reinterpret_cast<float4*>(&b_frag[4]) =
                *reinterpret_cast<const float4*>(&Bs[k][tx * TN + 4]);

            #pragma unroll
            for (int i = 0; i < TM; i++)
                #pragma unroll
                for (int j = 0; j < TN; j++)
                    acc[i][j] = fmaf(a_frag[i], b_frag[j], acc[i][j]);
        }
        __syncthreads();
    }

    // ---- epilogue: add bias, store float4
    #pragma unroll
    for (int i = 0; i < TM; i++) {
        int m = bm + ty * TM + i;
        float* Crow = C + (size_t)m * N + bn + tx * TN;
        #pragma unroll
        for (int j = 0; j < TN; j += 4) {
            int n = bn + tx * TN + j;
            float4 v;
            v.x = acc[i][j + 0] + bias[n + 0];
            v.y = acc[i][j + 1] + bias[n + 1];
            v.z = acc[i][j + 2] + bias[n + 2];
            v.w = acc[i][j + 3] + bias[n + 3];
            *reinterpret_cast<float4*>(Crow + j) = v;
        }
    }
}

extern "C" void kernel_launch(void* const* d_in, const int* in_sizes, int n_in,
                              void* d_out, int out_size)
{
    const float* x    = (const float*)d_in[0];   // [M, K]
    const float* w    = (const float*)d_in[1];   // [N, K]
    const float* bias = (const float*)d_in[2];   // [N]
    float* out        = (float*)d_out;           // [M, N]

    const int N = in_sizes[2];                   // 4096
    const int K = in_sizes[1] / N;               // 1024
    const int M = in_sizes[0] / K;               // 8192

    dim3 block(256);
    dim3 grid(N / BN, M / BM);                   // (32, 64)
    qlinear_sgemm_kernel<<<grid, block>>>(x, w, bias, out, M, N, K);
}

// round 3
// speedup vs baseline: 2.3483x; 2.3483x over previous
#include <cuda_runtime.h>
#include <cuda_bf16.h>
#include <cstdint>

// out[M,N] = x[M,K] @ W[N,K]^T + bias ; M=8192, N=4096, K=1024 (fp32)
// bf16x3 split-precision GEMM on mma.sync (base-PTX HMMA path; tcgen05 PTX is
// rejected because the toolchain emits compute_103 PTX without the 'a' suffix).

#define MDIM 8192
#define NDIM 4096
#define KDIM 1024

#define BM 128
#define BN 128
#define BK 32
#define STAGES 3
#define NCHUNK (KDIM / BK)      // 32

#define ROWB 80                 // padded smem row: 32 bf16 = 64B data + 16B pad
#define MATB (128 * ROWB)       // 10240 B per matrix tile
#define STAGEB (4 * MATB)       // 40960 B per stage (Ah, Al, Bh, Bl)
#define SMEM_TOTAL (STAGES * STAGEB)  // 122880 B

// ---- static scratch for split operands (allocation-free rule) ----
__device__ __align__(256) __nv_bfloat16 g_Ah[MDIM * KDIM];
__device__ __align__(256) __nv_bfloat16 g_Al[MDIM * KDIM];
__device__ __align__(256) __nv_bfloat16 g_Bh[NDIM * KDIM];
__device__ __align__(256) __nv_bfloat16 g_Bl[NDIM * KDIM];

// ================= PTX helpers (base PTX only, no 'a' features) =================
__device__ __forceinline__ uint32_t smem_u32(const void* p) {
    uint32_t a;
    asm("{ .reg .u64 t; cvta.to.shared.u64 t, %1; cvt.u32.u64 %0, t; }" : "=r"(a) : "l"(p));
    return a;
}
__device__ __forceinline__ void cp16(uint32_t dst, const void* src) {
    asm volatile("cp.async.cg.shared.global [%0], [%1], 16;" :: "r"(dst), "l"(src));
}
#define CP_COMMIT() asm volatile("cp.async.commit_group;" ::: "memory")
#define CP_WAIT1()  asm volatile("cp.async.wait_group 1;"  ::: "memory")
#define CP_WAIT0()  asm volatile("cp.async.wait_group 0;"  ::: "memory")

__device__ __forceinline__ void ldm_x4(uint32_t* r, uint32_t addr) {
    asm volatile("ldmatrix.sync.aligned.m8n8.x4.shared.b16 {%0,%1,%2,%3}, [%4];"
        : "=r"(r[0]), "=r"(r[1]), "=r"(r[2]), "=r"(r[3]) : "r"(addr));
}
__device__ __forceinline__ void mma16816(float* d, const uint32_t* a, const uint32_t* b) {
    asm volatile("mma.sync.aligned.m16n8k16.row.col.f32.bf16.bf16.f32 "
        "{%0,%1,%2,%3}, {%4,%5,%6,%7}, {%8,%9}, {%0,%1,%2,%3};"
        : "+f"(d[0]), "+f"(d[1]), "+f"(d[2]), "+f"(d[3])
        : "r"(a[0]), "r"(a[1]), "r"(a[2]), "r"(a[3]), "r"(b[0]), "r"(b[1]));
}

// ================= split kernel: fp32 -> (bf16 hi, bf16 lo) =================
__global__ void split_kernel(const float* __restrict__ src,
                             __nv_bfloat16* __restrict__ hi,
                             __nv_bfloat16* __restrict__ lo, int n4)
{
    int i = blockIdx.x * blockDim.x + threadIdx.x;
    if (i >= n4) return;
    float4 v = reinterpret_cast<const float4*>(src)[i];
    float vs[4] = {v.x, v.y, v.z, v.w};
    unsigned short hs[4], ls[4];
    #pragma unroll
    for (int j = 0; j < 4; j++) {
        __nv_bfloat16 h = __float2bfloat16(vs[j]);
        __nv_bfloat16 l = __float2bfloat16(vs[j] - __bfloat162float(h));
        hs[j] = ((__nv_bfloat16_raw)h).x;
        ls[j] = ((__nv_bfloat16_raw)l).x;
    }
    ushort4 ho = {hs[0], hs[1], hs[2], hs[3]};
    ushort4 lv = {ls[0], ls[1], ls[2], ls[3]};
    reinterpret_cast<ushort4*>(hi)[i] = ho;
    reinterpret_cast<ushort4*>(lo)[i] = lv;
}

// ================= main GEMM kernel =================
__global__ void __launch_bounds__(256, 1)
qgemm_mma(const __nv_bfloat16* __restrict__ Ah, const __nv_bfloat16* __restrict__ Al,
          const __nv_bfloat16* __restrict__ Bh, const __nv_bfloat16* __restrict__ Bl,
          const float* __restrict__ bias, float* __restrict__ C)
{
    extern __shared__ char smem[];
    const uint32_t sbase = smem_u32(smem);
    const int tid  = threadIdx.x;
    const int wid  = tid >> 5;
    const int lane = tid & 31;
    const int bm = blockIdx.y * BM;
    const int bn = blockIdx.x * BN;
    const int wm = (wid >> 2) * 64;   // warp row offset in CTA tile
    const int wn = (wid & 3) * 32;    // warp col offset in CTA tile

    // per-thread cp.async coords: each thread copies 8 x 16B chunks per stage
    const int lrow = tid >> 2;        // 0..63
    const int lc   = tid & 3;         // 16B chunk within 64B row

    const char* gA[2] = {(const char*)Ah, (const char*)Al};
    const char* gB[2] = {(const char*)Bh, (const char*)Bl};

    float acc[4][4][4];
    #pragma unroll
    for (int i = 0; i < 4; i++)
        #pragma unroll
        for (int j = 0; j < 4; j++)
            #pragma unroll
            for (int k = 0; k < 4; k++)
                acc[i][j][k] = 0.0f;

    // -------- async load of one k-chunk into one stage buffer --------
    auto issue_stage = [&](int chunk, int stage) {
        const uint32_t sst = sbase + stage * STAGEB;
        const size_t kbyte = (size_t)chunk * BK * 2 + lc * 16;
        #pragma unroll
        for (int h = 0; h < 2; h++) {
            cp16(sst + h * MATB + lrow * ROWB + lc * 16,
                 gA[h] + (size_t)(bm + lrow) * (KDIM * 2) + kbyte);
            cp16(sst + h * MATB + (lrow + 64) * ROWB + lc * 16,
                 gA[h] + (size_t)(bm + lrow + 64) * (KDIM * 2) + kbyte);
            cp16(sst + (2 + h) * MATB + lrow * ROWB + lc * 16,
                 gB[h] + (size_t)(bn + lrow) * (KDIM * 2) + kbyte);
            cp16(sst + (2 + h) * MATB + (lrow + 64) * ROWB + lc * 16,
                 gB[h] + (size_t)(bn + lrow + 64) * (KDIM * 2) + kbyte);
        }
        CP_COMMIT();
    };

    // prologue: fill 2 of 3 stages
    issue_stage(0, 0);
    issue_stage(1, 1);

    // ldmatrix lane addressing (precomputed)
    const int a_row   = wm + (lane & 15);
    const uint32_t a_ch = ((uint32_t)(lane >> 4)) * 16;          // k-chunk select
    const int b_row   = wn + (lane & 7) + ((lane >> 4) & 1) * 8; // n-row
    const uint32_t b_ch = ((uint32_t)((lane >> 3) & 1)) * 16;

    for (int c = 0; c < NCHUNK; c++) {
        CP_WAIT1();
        __syncthreads();
        if (c + 2 < NCHUNK) issue_stage(c + 2, (c + 2) % STAGES);

        const uint32_t sst = sbase + (c % STAGES) * STAGEB;
        #pragma unroll
        for (int ks = 0; ks < 2; ks++) {               // two k16 steps per BK=32
            uint32_t ah[4][4], al[4][4], bh[4][2], bl[4][2];
            #pragma unroll
            for (int mb = 0; mb < 4; mb++) {
                uint32_t addr = sst + (a_row + mb * 16) * ROWB + ks * 32 + a_ch;
                ldm_x4(ah[mb], addr);
                ldm_x4(al[mb], addr + MATB);
            }
            #pragma unroll
            for (int p = 0; p < 2; p++) {              // 2 n16 pairs -> 4 n8 blocks
                uint32_t r[4];
                uint32_t addr = sst + 2 * MATB + (b_row + p * 16) * ROWB + ks * 32 + b_ch;
                ldm_x4(r, addr);
                bh[p*2][0] = r[0]; bh[p*2][1] = r[1];
                bh[p*2+1][0] = r[2]; bh[p*2+1][1] = r[3];
                ldm_x4(r, addr + MATB);
                bl[p*2][0] = r[0]; bl[p*2][1] = r[1];
                bl[p*2+1][0] = r[2]; bl[p*2+1][1] = r[3];
            }
            #pragma unroll
            for (int mb = 0; mb < 4; mb++)
                #pragma unroll
                for (int nb = 0; nb < 4; nb++) {
                    mma16816(acc[mb][nb], ah[mb], bh[nb]);
                    mma16816(acc[mb][nb], ah[mb], bl[nb]);
                    mma16816(acc[mb][nb], al[mb], bh[nb]);
                }
        }
    }
    CP_WAIT0();

    // -------- epilogue: + bias, store --------
    const int g  = lane >> 2;
    const int tg = lane & 3;
    #pragma unroll
    for (int mb = 0; mb < 4; mb++) {
        #pragma unroll
        for (int nb = 0; nb < 4; nb++) {
            const int col = bn + wn + nb * 8 + tg * 2;
            const float2 bv = *reinterpret_cast<const float2*>(bias + col);
            const int r0 = bm + wm + mb * 16 + g;
            float2 o0 = {acc[mb][nb][0] + bv.x, acc[mb][nb][1] + bv.y};
            float2 o1 = {acc[mb][nb][2] + bv.x, acc[mb][nb][3] + bv.y};
            *reinterpret_cast<float2*>(C + (size_t)r0 * NDIM + col) = o0;
            *reinterpret_cast<float2*>(C + (size_t)(r0 + 8) * NDIM + col) = o1;
        }
    }
}

// ================= host side =================
extern "C" void kernel_launch(void* const* d_in, const int* in_sizes, int n_in,
                              void* d_out, int out_size)
{
    const float* x    = (const float*)d_in[0];   // [M, K]
    const float* w    = (const float*)d_in[1];   // [N, K]
    const float* bias = (const float*)d_in[2];   // [N]
    float* out        = (float*)d_out;           // [M, N]

    void *pAh, *pAl, *pBh, *pBl;
    cudaGetSymbolAddress(&pAh, g_Ah);
    cudaGetSymbolAddress(&pAl, g_Al);
    cudaGetSymbolAddress(&pBh, g_Bh);
    cudaGetSymbolAddress(&pBl, g_Bl);

    // 1) split x and w into bf16 hi/lo
    int n4a = MDIM * KDIM / 4;
    int n4b = NDIM * KDIM / 4;
    split_kernel<<<(n4a + 255) / 256, 256>>>(x, (__nv_bfloat16*)pAh, (__nv_bfloat16*)pAl, n4a);
    split_kernel<<<(n4b + 255) / 256, 256>>>(w, (__nv_bfloat16*)pBh, (__nv_bfloat16*)pBl, n4b);

    // 2) HMMA GEMM
    static bool attr_set = false;
    if (!attr_set) {
        cudaFuncSetAttribute(qgemm_mma, cudaFuncAttributeMaxDynamicSharedMemorySize, SMEM_TOTAL);
        attr_set = true;
    }
    dim3 grid(NDIM / BN, MDIM / BM);   // (32, 64)
    qgemm_mma<<<grid, 256, SMEM_TOTAL>>>((const __nv_bfloat16*)pAh, (const __nv_bfloat16*)pAl,
                                         (const __nv_bfloat16*)pBh, (const __nv_bfloat16*)pBl,
                                         bias, out);
}

// round 4
// speedup vs baseline: 2.8542x; 1.2154x over previous
#include <cuda_runtime.h>
#include <cuda_bf16.h>
#include <cstdint>

// out[M,N] = x[M,K] @ W[N,K]^T + bias ; M=8192, N=4096, K=1024 (fp32)
// bf16x3 split-precision GEMM on mma.sync HMMA (base PTX).
// Round 4: 512-thread CTA (4 warps/SMSP), 256x128 tile, low-frag-pressure loop.

#define MDIM 8192
#define NDIM 4096
#define KDIM 1024

#define BM 256
#define BN 128
#define BK 32
#define STAGES 3
#define NCHUNK (KDIM / BK)      // 32

#define ROWB 80                 // padded smem row: 32 bf16 = 64B + 16B pad
#define OFF_AH 0
#define OFF_AL (256 * ROWB)     // 20480
#define OFF_BH (512 * ROWB)     // 40960
#define OFF_BL (640 * ROWB)     // 51200
#define STAGEB (768 * ROWB)     // 61440
#define SMEM_TOTAL (STAGES * STAGEB)  // 184320

// ---- static scratch for split operands ----
__device__ __align__(256) __nv_bfloat16 g_Ah[MDIM * KDIM];
__device__ __align__(256) __nv_bfloat16 g_Al[MDIM * KDIM];
__device__ __align__(256) __nv_bfloat16 g_Bh[NDIM * KDIM];
__device__ __align__(256) __nv_bfloat16 g_Bl[NDIM * KDIM];

// ================= PTX helpers (base PTX only) =================
__device__ __forceinline__ uint32_t smem_u32(const void* p) {
    uint32_t a;
    asm("{ .reg .u64 t; cvta.to.shared.u64 t, %1; cvt.u32.u64 %0, t; }" : "=r"(a) : "l"(p));
    return a;
}
__device__ __forceinline__ void cp16(uint32_t dst, const void* src) {
    asm volatile("cp.async.cg.shared.global [%0], [%1], 16;" :: "r"(dst), "l"(src));
}
#define CP_COMMIT() asm volatile("cp.async.commit_group;" ::: "memory")
#define CP_WAIT1()  asm volatile("cp.async.wait_group 1;"  ::: "memory")
#define CP_WAIT0()  asm volatile("cp.async.wait_group 0;"  ::: "memory")

__device__ __forceinline__ void ldm_x4(uint32_t* r, uint32_t addr) {
    asm volatile("ldmatrix.sync.aligned.m8n8.x4.shared.b16 {%0,%1,%2,%3}, [%4];"
        : "=r"(r[0]), "=r"(r[1]), "=r"(r[2]), "=r"(r[3]) : "r"(addr));
}
__device__ __forceinline__ void mma16816(float* d, const uint32_t* a, const uint32_t* b) {
    asm volatile("mma.sync.aligned.m16n8k16.row.col.f32.bf16.bf16.f32 "
        "{%0,%1,%2,%3}, {%4,%5,%6,%7}, {%8,%9}, {%0,%1,%2,%3};"
        : "+f"(d[0]), "+f"(d[1]), "+f"(d[2]), "+f"(d[3])
        : "r"(a[0]), "r"(a[1]), "r"(a[2]), "r"(a[3]), "r"(b[0]), "r"(b[1]));
}

// ================= split kernel: fp32 -> (bf16 hi, bf16 lo) =================
__global__ void split_kernel(const float* __restrict__ src,
                             __nv_bfloat16* __restrict__ hi,
                             __nv_bfloat16* __restrict__ lo, int n4)
{
    int i = blockIdx.x * blockDim.x + threadIdx.x;
    if (i >= n4) return;
    float4 v = reinterpret_cast<const float4*>(src)[i];
    float vs[4] = {v.x, v.y, v.z, v.w};
    unsigned short hs[4], ls[4];
    #pragma unroll
    for (int j = 0; j < 4; j++) {
        __nv_bfloat16 h = __float2bfloat16(vs[j]);
        __nv_bfloat16 l = __float2bfloat16(vs[j] - __bfloat162float(h));
        hs[j] = ((__nv_bfloat16_raw)h).x;
        ls[j] = ((__nv_bfloat16_raw)l).x;
    }
    ushort4 ho = {hs[0], hs[1], hs[2], hs[3]};
    ushort4 lv = {ls[0], ls[1], ls[2], ls[3]};
    reinterpret_cast<ushort4*>(hi)[i] = ho;
    reinterpret_cast<ushort4*>(lo)[i] = lv;
}

// ================= main GEMM kernel =================
__global__ void __launch_bounds__(512, 1)
qgemm_mma(const __nv_bfloat16* __restrict__ Ah, const __nv_bfloat16* __restrict__ Al,
          const __nv_bfloat16* __restrict__ Bh, const __nv_bfloat16* __restrict__ Bl,
          const float* __restrict__ bias, float* __restrict__ C)
{
    extern __shared__ char smem[];
    const uint32_t sbase = smem_u32(smem);
    const int tid  = threadIdx.x;
    const int wid  = tid >> 5;
    const int lane = tid & 31;
    const int bm = blockIdx.y * BM;
    const int bn = blockIdx.x * BN;
    const int wm = (wid >> 2) * 64;   // warp row offset (0..192)
    const int wn = (wid & 3) * 32;    // warp col offset (0..96)

    // cp.async coords: 512 threads, each copies 6 x 16B per stage
    const int lrow = tid >> 2;        // 0..127
    const int lc   = tid & 3;

    float acc[4][4][4];
    #pragma unroll
    for (int i = 0; i < 4; i++)
        #pragma unroll
        for (int j = 0; j < 4; j++)
            #pragma unroll
            for (int k = 0; k < 4; k++)
                acc[i][j][k] = 0.0f;

    auto issue_stage = [&](int chunk, int stage) {
        const uint32_t sst = sbase + stage * STAGEB;
        const size_t kbyte = (size_t)chunk * (BK * 2) + lc * 16;
        const uint32_t dst = sst + lrow * ROWB + lc * 16;
        const size_t rowb0 = (size_t)(bm + lrow) * (KDIM * 2) + kbyte;
        const size_t rowb1 = (size_t)(bm + 128 + lrow) * (KDIM * 2) + kbyte;
        const size_t rowbB = (size_t)(bn + lrow) * (KDIM * 2) + kbyte;
        cp16(dst,                        (const char*)Ah + rowb0);
        cp16(dst + 128 * ROWB,           (const char*)Ah + rowb1);
        cp16(dst + OFF_AL,               (const char*)Al + rowb0);
        cp16(dst + OFF_AL + 128 * ROWB,  (const char*)Al + rowb1);
        cp16(dst + OFF_BH,               (const char*)Bh + rowbB);
        cp16(dst + OFF_BL,               (const char*)Bl + rowbB);
        CP_COMMIT();
    };

    issue_stage(0, 0);
    issue_stage(1, 1);

    // ldmatrix lane addressing
    const uint32_t a_off = (uint32_t)(wm + (lane & 15)) * ROWB + ((uint32_t)(lane >> 4)) * 16;
    const uint32_t b_off = OFF_BH +
        (uint32_t)(wn + (lane & 7) + ((lane >> 4) & 1) * 8) * ROWB +
        ((uint32_t)((lane >> 3) & 1)) * 16;

    for (int c = 0; c < NCHUNK; c++) {
        CP_WAIT1();
        __syncthreads();
        if (c + 2 < NCHUNK) issue_stage(c + 2, (c + 2) % STAGES);

        const uint32_t sst = sbase + (c % STAGES) * STAGEB;
        #pragma unroll
        for (int ks = 0; ks < 2; ks++) {
            // B fragments: hi & lo for all 4 n8 blocks (24 regs live)
            uint32_t bh[4][2], bl[4][2];
            #pragma unroll
            for (int p = 0; p < 2; p++) {
                uint32_t r[4];
                uint32_t addr = sst + b_off + p * (16 * ROWB) + ks * 32;
                ldm_x4(r, addr);
                bh[p*2][0] = r[0]; bh[p*2][1] = r[1];
                bh[p*2+1][0] = r[2]; bh[p*2+1][1] = r[3];
                ldm_x4(r, addr + (OFF_BL - OFF_BH));
                bl[p*2][0] = r[0]; bl[p*2][1] = r[1];
                bl[p*2+1][0] = r[2]; bl[p*2+1][1] = r[3];
            }
            // stream A fragments per 16-row block, consume immediately
            #pragma unroll
            for (int mb = 0; mb < 4; mb++) {
                uint32_t ah[4], al[4];
                uint32_t addr = sst + a_off + mb * (16 * ROWB) + ks * 32;
                ldm_x4(ah, addr);
                ldm_x4(al, addr + OFF_AL);
                #pragma unroll
                for (int nb = 0; nb < 4; nb++) {
                    mma16816(acc[mb][nb], ah, bh[nb]);
                    mma16816(acc[mb][nb], ah, bl[nb]);
                    mma16816(acc[mb][nb], al, bh[nb]);
                }
            }
        }
    }
    CP_WAIT0();

    // -------- epilogue: + bias, store --------
    const int g  = lane >> 2;
    const int tg = lane & 3;
    #pragma unroll
    for (int mb = 0; mb < 4; mb++) {
        #pragma unroll
        for (int nb = 0; nb < 4; nb++) {
            const int col = bn + wn + nb * 8 + tg * 2;
            const float2 bv = *reinterpret_cast<const float2*>(bias + col);
            const int r0 = bm + wm + mb * 16 + g;
            float2 o0 = {acc[mb][nb][0] + bv.x, acc[mb][nb][1] + bv.y};
            float2 o1 = {acc[mb][nb][2] + bv.x, acc[mb][nb][3] + bv.y};
            *reinterpret_cast<float2*>(C + (size_t)r0 * NDIM + col) = o0;
            *reinterpret_cast<float2*>(C + (size_t)(r0 + 8) * NDIM + col) = o1;
        }
    }
}

// ================= host side =================
extern "C" void kernel_launch(void* const* d_in, const int* in_sizes, int n_in,
                              void* d_out, int out_size)
{
    const float* x    = (const float*)d_in[0];   // [M, K]
    const float* w    = (const float*)d_in[1];   // [N, K]
    const float* bias = (const float*)d_in[2];   // [N]
    float* out        = (float*)d_out;           // [M, N]

    void *pAh, *pAl, *pBh, *pBl;
    cudaGetSymbolAddress(&pAh, g_Ah);
    cudaGetSymbolAddress(&pAl, g_Al);
    cudaGetSymbolAddress(&pBh, g_Bh);
    cudaGetSymbolAddress(&pBl, g_Bl);

    int n4a = MDIM * KDIM / 4;
    int n4b = NDIM * KDIM / 4;
    split_kernel<<<(n4a + 255) / 256, 256>>>(x, (__nv_bfloat16*)pAh, (__nv_bfloat16*)pAl, n4a);
    split_kernel<<<(n4b + 255) / 256, 256>>>(w, (__nv_bfloat16*)pBh, (__nv_bfloat16*)pBl, n4b);

    static bool attr_set = false;
    if (!attr_set) {
        cudaFuncSetAttribute(qgemm_mma, cudaFuncAttributeMaxDynamicSharedMemorySize, SMEM_TOTAL);
        attr_set = true;
    }
    dim3 grid(NDIM / BN, MDIM / BM);   // (32, 32)
    qgemm_mma<<<grid, 512, SMEM_TOTAL>>>((const __nv_bfloat16*)pAh, (const __nv_bfloat16*)pAl,
                                         (const __nv_bfloat16*)pBh, (const __nv_bfloat16*)pBl,
                                         bias, out);
}

// round 5
// speedup vs baseline: 2.8611x; 1.0024x over previous
#include <cuda_runtime.h>
#include <cuda_bf16.h>
#include <cstdint>

// out[M,N] = x[M,K] @ W[N,K]^T + bias ; M=8192, N=4096, K=1024 (fp32)
// bf16x3 split-precision GEMM on mma.sync HMMA (base PTX).
// Round 5: break accumulator RAW chains (term-major inner loop), merged split.

#define MDIM 8192
#define NDIM 4096
#define KDIM 1024

#define BM 256
#define BN 128
#define BK 32
#define STAGES 3
#define NCHUNK (KDIM / BK)      // 32

#define ROWB 80                 // padded smem row: 32 bf16 = 64B + 16B pad
#define OFF_AH 0
#define OFF_AL (256 * ROWB)     // 20480
#define OFF_BH (512 * ROWB)     // 40960
#define OFF_BL (640 * ROWB)     // 51200
#define STAGEB (768 * ROWB)     // 61440
#define SMEM_TOTAL (STAGES * STAGEB)  // 184320

// ---- static scratch for split operands ----
__device__ __align__(256) __nv_bfloat16 g_Ah[MDIM * KDIM];
__device__ __align__(256) __nv_bfloat16 g_Al[MDIM * KDIM];
__device__ __align__(256) __nv_bfloat16 g_Bh[NDIM * KDIM];
__device__ __align__(256) __nv_bfloat16 g_Bl[NDIM * KDIM];

// ================= PTX helpers (base PTX only) =================
__device__ __forceinline__ uint32_t smem_u32(const void* p) {
    uint32_t a;
    asm("{ .reg .u64 t; cvta.to.shared.u64 t, %1; cvt.u32.u64 %0, t; }" : "=r"(a) : "l"(p));
    return a;
}
__device__ __forceinline__ void cp16(uint32_t dst, const void* src) {
    asm volatile("cp.async.cg.shared.global [%0], [%1], 16;" :: "r"(dst), "l"(src));
}
#define CP_COMMIT() asm volatile("cp.async.commit_group;" ::: "memory")
#define CP_WAIT1()  asm volatile("cp.async.wait_group 1;"  ::: "memory")
#define CP_WAIT0()  asm volatile("cp.async.wait_group 0;"  ::: "memory")

__device__ __forceinline__ void ldm_x4(uint32_t* r, uint32_t addr) {
    asm volatile("ldmatrix.sync.aligned.m8n8.x4.shared.b16 {%0,%1,%2,%3}, [%4];"
        : "=r"(r[0]), "=r"(r[1]), "=r"(r[2]), "=r"(r[3]) : "r"(addr));
}
__device__ __forceinline__ void mma16816(float* d, const uint32_t* a, const uint32_t* b) {
    asm volatile("mma.sync.aligned.m16n8k16.row.col.f32.bf16.bf16.f32 "
        "{%0,%1,%2,%3}, {%4,%5,%6,%7}, {%8,%9}, {%0,%1,%2,%3};"
        : "+f"(d[0]), "+f"(d[1]), "+f"(d[2]), "+f"(d[3])
        : "r"(a[0]), "r"(a[1]), "r"(a[2]), "r"(a[3]), "r"(b[0]), "r"(b[1]));
}

// ================= merged split kernel: fp32 -> (bf16 hi, bf16 lo) =================
// One launch covers both x (n4a float4s) and w (n4b float4s).
__global__ void split_both_kernel(const float* __restrict__ srcA,
                                  const float* __restrict__ srcB,
                                  __nv_bfloat16* __restrict__ hiA, __nv_bfloat16* __restrict__ loA,
                                  __nv_bfloat16* __restrict__ hiB, __nv_bfloat16* __restrict__ loB,
                                  int n4a, int n4tot)
{
    int i = blockIdx.x * blockDim.x + threadIdx.x;
    if (i >= n4tot) return;
    const float* src;
    __nv_bfloat16 *hi, *lo;
    int idx;
    if (i < n4a) { src = srcA; hi = hiA; lo = loA; idx = i; }
    else         { src = srcB; hi = hiB; lo = loB; idx = i - n4a; }

    float4 v = reinterpret_cast<const float4*>(src)[idx];
    float vs[4] = {v.x, v.y, v.z, v.w};
    unsigned short hs[4], ls[4];
    #pragma unroll
    for (int j = 0; j < 4; j++) {
        __nv_bfloat16 h = __float2bfloat16(vs[j]);
        __nv_bfloat16 l = __float2bfloat16(vs[j] - __bfloat162float(h));
        hs[j] = ((__nv_bfloat16_raw)h).x;
        ls[j] = ((__nv_bfloat16_raw)l).x;
    }
    ushort4 ho = {hs[0], hs[1], hs[2], hs[3]};
    ushort4 lv = {ls[0], ls[1], ls[2], ls[3]};
    reinterpret_cast<ushort4*>(hi)[idx] = ho;
    reinterpret_cast<ushort4*>(lo)[idx] = lv;
}

// ================= main GEMM kernel =================
__global__ void __launch_bounds__(512, 1)
qgemm_mma(const __nv_bfloat16* __restrict__ Ah, const __nv_bfloat16* __restrict__ Al,
          const __nv_bfloat16* __restrict__ Bh, const __nv_bfloat16* __restrict__ Bl,
          const float* __restrict__ bias, float* __restrict__ C)
{
    extern __shared__ char smem[];
    const uint32_t sbase = smem_u32(smem);
    const int tid  = threadIdx.x;
    const int wid  = tid >> 5;
    const int lane = tid & 31;
    const int bm = blockIdx.y * BM;
    const int bn = blockIdx.x * BN;
    const int wm = (wid >> 2) * 64;   // warp row offset (0..192)
    const int wn = (wid & 3) * 32;    // warp col offset (0..96)

    // cp.async coords: 512 threads, each copies 6 x 16B per stage
    const int lrow = tid >> 2;        // 0..127
    const int lc   = tid & 3;

    float acc[4][4][4];
    #pragma unroll
    for (int i = 0; i < 4; i++)
        #pragma unroll
        for (int j = 0; j < 4; j++)
            #pragma unroll
            for (int k = 0; k < 4; k++)
                acc[i][j][k] = 0.0f;

    auto issue_stage = [&](int chunk, int stage) {
        const uint32_t sst = sbase + stage * STAGEB;
        const size_t kbyte = (size_t)chunk * (BK * 2) + lc * 16;
        const uint32_t dst = sst + lrow * ROWB + lc * 16;
        const size_t rowb0 = (size_t)(bm + lrow) * (KDIM * 2) + kbyte;
        const size_t rowb1 = (size_t)(bm + 128 + lrow) * (KDIM * 2) + kbyte;
        const size_t rowbB = (size_t)(bn + lrow) * (KDIM * 2) + kbyte;
        cp16(dst,                        (const char*)Ah + rowb0);
        cp16(dst + 128 * ROWB,           (const char*)Ah + rowb1);
        cp16(dst + OFF_AL,               (const char*)Al + rowb0);
        cp16(dst + OFF_AL + 128 * ROWB,  (const char*)Al + rowb1);
        cp16(dst + OFF_BH,               (const char*)Bh + rowbB);
        cp16(dst + OFF_BL,               (const char*)Bl + rowbB);
        CP_COMMIT();
    };

    issue_stage(0, 0);
    issue_stage(1, 1);

    // ldmatrix lane addressing
    const uint32_t a_off = (uint32_t)(wm + (lane & 15)) * ROWB + ((uint32_t)(lane >> 4)) * 16;
    const uint32_t b_off = OFF_BH +
        (uint32_t)(wn + (lane & 7) + ((lane >> 4) & 1) * 8) * ROWB +
        ((uint32_t)((lane >> 3) & 1)) * 16;

    for (int c = 0; c < NCHUNK; c++) {
        CP_WAIT1();
        __syncthreads();
        if (c + 2 < NCHUNK) issue_stage(c + 2, (c + 2) % STAGES);

        const uint32_t sst = sbase + (c % STAGES) * STAGEB;
        #pragma unroll
        for (int ks = 0; ks < 2; ks++) {
            // B fragments: hi & lo for all 4 n8 blocks
            uint32_t bh[4][2], bl[4][2];
            #pragma unroll
            for (int p = 0; p < 2; p++) {
                uint32_t r[4];
                uint32_t addr = sst + b_off + p * (16 * ROWB) + ks * 32;
                ldm_x4(r, addr);
                bh[p*2][0] = r[0]; bh[p*2][1] = r[1];
                bh[p*2+1][0] = r[2]; bh[p*2+1][1] = r[3];
                ldm_x4(r, addr + (OFF_BL - OFF_BH));
                bl[p*2][0] = r[0]; bl[p*2][1] = r[1];
                bl[p*2+1][0] = r[2]; bl[p*2+1][1] = r[3];
            }
            // stream A fragments per 16-row block; TERM-MAJOR issue order so
            // writes to the same accumulator are >= 4 MMAs apart (no RAW chain)
            #pragma unroll
            for (int mb = 0; mb < 4; mb++) {
                uint32_t ah[4], al[4];
                uint32_t addr = sst + a_off + mb * (16 * ROWB) + ks * 32;
                ldm_x4(ah, addr);
                ldm_x4(al, addr + OFF_AL);
                #pragma unroll
                for (int nb = 0; nb < 4; nb++)
                    mma16816(acc[mb][nb], ah, bh[nb]);
                #pragma unroll
                for (int nb = 0; nb < 4; nb++)
                    mma16816(acc[mb][nb], ah, bl[nb]);
                #pragma unroll
                for (int nb = 0; nb < 4; nb++)
                    mma16816(acc[mb][nb], al, bh[nb]);
            }
        }
    }
    CP_WAIT0();

    // -------- epilogue: + bias, store --------
    const int g  = lane >> 2;
    const int tg = lane & 3;
    #pragma unroll
    for (int mb = 0; mb < 4; mb++) {
        #pragma unroll
        for (int nb = 0; nb < 4; nb++) {
            const int col = bn + wn + nb * 8 + tg * 2;
            const float2 bv = *reinterpret_cast<const float2*>(bias + col);
            const int r0 = bm + wm + mb * 16 + g;
            float2 o0 = {acc[mb][nb][0] + bv.x, acc[mb][nb][1] + bv.y};
            float2 o1 = {acc[mb][nb][2] + bv.x, acc[mb][nb][3] + bv.y};
            *reinterpret_cast<float2*>(C + (size_t)r0 * NDIM + col) = o0;
            *reinterpret_cast<float2*>(C + (size_t)(r0 + 8) * NDIM + col) = o1;
        }
    }
}

// ================= host side =================
extern "C" void kernel_launch(void* const* d_in, const int* in_sizes, int n_in,
                              void* d_out, int out_size)
{
    const float* x    = (const float*)d_in[0];   // [M, K]
    const float* w    = (const float*)d_in[1];   // [N, K]
    const float* bias = (const float*)d_in[2];   // [N]
    float* out        = (float*)d_out;           // [M, N]

    void *pAh, *pAl, *pBh, *pBl;
    cudaGetSymbolAddress(&pAh, g_Ah);
    cudaGetSymbolAddress(&pAl, g_Al);
    cudaGetSymbolAddress(&pBh, g_Bh);
    cudaGetSymbolAddress(&pBl, g_Bl);

    int n4a = MDIM * KDIM / 4;
    int n4b = NDIM * KDIM / 4;
    int n4tot = n4a + n4b;
    split_both_kernel<<<(n4tot + 255) / 256, 256>>>(
        x, w,
        (__nv_bfloat16*)pAh, (__nv_bfloat16*)pAl,
        (__nv_bfloat16*)pBh, (__nv_bfloat16*)pBl, n4a, n4tot);

    static bool attr_set = false;
    if (!attr_set) {
        cudaFuncSetAttribute(qgemm_mma, cudaFuncAttributeMaxDynamicSharedMemorySize, SMEM_TOTAL);
        attr_set = true;
    }
    dim3 grid(NDIM / BN, MDIM / BM);   // (32, 32)
    qgemm_mma<<<grid, 512, SMEM_TOTAL>>>((const __nv_bfloat16*)pAh, (const __nv_bfloat16*)pAl,
                                         (const __nv_bfloat16*)pBh, (const __nv_bfloat16*)pBl,
                                         bias, out);
}